// round 14
// baseline (speedup 1.0000x reference)
#include <cuda_runtime.h>
#include <cuda_bf16.h>
#include <cstdint>

// Problem dims (fixed)
static constexpr int Mdim = 16384;   // B*S
static constexpr int Ndim = 16384;   // DOUT
static constexpr int Kdim = 4096;    // DIN

// GEMM tiling: CTA 128x256, 8 warps (2x4), warp tile 64x64, BK=64, 3 stages
static constexpr int BM = 128, BN = 256, BK = 64;
static constexpr int STAGES = 3;
static constexpr int THREADS = 256;
static constexpr int KTILES = Kdim / BK;     // 64

// Scratch (device globals; no allocation). 128 MiB each.
__device__ __nv_bfloat16 g_wdeq[(size_t)Ndim * Kdim];
__device__ __nv_bfloat16 g_xbf [(size_t)Mdim * Kdim];

// ---------------------------------------------------------------------------
// Pre-pass 1: dequant. w int32, s fp32(bf16-valued) -> bf16 (single rounding
// of exact product == reference's bf16*bf16 multiply)
// ---------------------------------------------------------------------------
__global__ __launch_bounds__(256) void dequant_kernel(
    const int* __restrict__ w, const float* __restrict__ s)
{
    size_t q = (size_t)blockIdx.x * 256 + threadIdx.x;     // one int4 = 4 weights
    int row = (int)(q >> 10);                               // Kdim/4 quads per row
    float sc = s[row];
    int4 qv = reinterpret_cast<const int4*>(w)[q];
    __nv_bfloat162 r01 = __floats2bfloat162_rn((float)qv.x * sc, (float)qv.y * sc);
    __nv_bfloat162 r23 = __floats2bfloat162_rn((float)qv.z * sc, (float)qv.w * sc);
    __nv_bfloat162 pack[2] = {r01, r23};
    *reinterpret_cast<uint2*>(&g_wdeq[q * 4]) = *reinterpret_cast<uint2*>(pack);
}

// ---------------------------------------------------------------------------
// Pre-pass 2: x fp32(bf16-valued) -> bf16 (exact)
// ---------------------------------------------------------------------------
__global__ __launch_bounds__(256) void xconv_kernel(const float* __restrict__ x)
{
    size_t q = (size_t)blockIdx.x * 256 + threadIdx.x;     // one float4
    float4 v = reinterpret_cast<const float4*>(x)[q];
    __nv_bfloat162 r01 = __floats2bfloat162_rn(v.x, v.y);
    __nv_bfloat162 r23 = __floats2bfloat162_rn(v.z, v.w);
    __nv_bfloat162 pack[2] = {r01, r23};
    *reinterpret_cast<uint2*>(&g_xbf[q * 4]) = *reinterpret_cast<uint2*>(pack);
}

// ---------------------------------------------------------------------------
// Helpers
// ---------------------------------------------------------------------------
__device__ __forceinline__ uint32_t smem_u32(const void* p) {
    return (uint32_t)__cvta_generic_to_shared(p);
}
__device__ __forceinline__ void cp_async16(uint32_t saddr, const void* g) {
    asm volatile("cp.async.cg.shared.global [%0], [%1], 16;\n" :: "r"(saddr), "l"(g));
}
__device__ __forceinline__ void cp_commit() { asm volatile("cp.async.commit_group;\n"); }
template<int N> __device__ __forceinline__ void cp_wait() {
    asm volatile("cp.async.wait_group %0;\n" :: "n"(N));
}
__device__ __forceinline__ void ldmatrix_x4(uint32_t &r0, uint32_t &r1,
                                            uint32_t &r2, uint32_t &r3, uint32_t addr) {
    asm volatile("ldmatrix.sync.aligned.m8n8.x4.shared.b16 {%0,%1,%2,%3}, [%4];\n"
                 : "=r"(r0), "=r"(r1), "=r"(r2), "=r"(r3) : "r"(addr));
}
__device__ __forceinline__ void mma_16816(float* c, const uint32_t* a, const uint32_t* b) {
    asm volatile(
        "mma.sync.aligned.m16n8k16.row.col.f32.bf16.bf16.f32 "
        "{%0,%1,%2,%3}, {%4,%5,%6,%7}, {%8,%9}, {%0,%1,%2,%3};\n"
        : "+f"(c[0]), "+f"(c[1]), "+f"(c[2]), "+f"(c[3])
        : "r"(a[0]), "r"(a[1]), "r"(a[2]), "r"(a[3]), "r"(b[0]), "r"(b[1]));
}
__device__ __forceinline__ float bf16r(float v) {
    return __bfloat162float(__float2bfloat16_rn(v));
}

// ---------------------------------------------------------------------------
// bf16 GEMM: C[M,N] = X[M,K] @ Wd[N,K]^T, fp32 accum, bf16-rounded fp32 out.
// CTA 128x256, 8 warps (2 warps/SMSP for latency hiding), warp tile 64x64.
// ---------------------------------------------------------------------------
__global__ __launch_bounds__(THREADS, 1) void gemm_kernel(float* __restrict__ C)
{
    extern __shared__ __nv_bfloat16 smem[];
    __nv_bfloat16* sA = smem;                               // STAGES * BM * BK
    __nv_bfloat16* sB = smem + (size_t)STAGES * BM * BK;    // STAGES * BN * BK

    // CTA swizzle: groups of 16 M-tiles, N fast within a group (L2 reuse)
    const int tiles_n = Ndim / BN;     // 64
    const int GROUP = 16;
    const int per_group = GROUP * tiles_n;
    const int g_ = blockIdx.x / per_group;
    const int r_ = blockIdx.x % per_group;
    const int bm = g_ * GROUP + (r_ % GROUP);
    const int bn = r_ / GROUP;

    const int tid  = threadIdx.x;
    const int warp = tid >> 5;
    const int lane = tid & 31;
    const int wm = warp >> 2;          // 0..1 -> 64-row half
    const int wn = warp & 3;           // 0..3 -> 64-col quarter
    const int lg  = lane >> 2;         // 0..7
    const int tig = lane & 3;          // 0..3

    const __nv_bfloat16* gA0 = g_xbf  + (size_t)(bm * BM) * Kdim;
    const __nv_bfloat16* gB0 = g_wdeq + (size_t)(bn * BN) * Kdim;

    // cp.async slots. A: 128 rows x 8 chunks = 1024 (4/thread).
    //                 B: 256 rows x 8 chunks = 2048 (8/thread).
    int arow[4], ach[4], asoff[4];
    #pragma unroll
    for (int i = 0; i < 4; i++) {
        int lin = tid + i * THREADS;
        arow[i]  = lin >> 3;
        ach[i]   = lin & 7;
        asoff[i] = arow[i] * BK + ((ach[i] ^ (arow[i] & 7)) << 3);
    }
    int brow[8], bch[8], bsoff[8];
    #pragma unroll
    for (int i = 0; i < 8; i++) {
        int lin = tid + i * THREADS;
        brow[i]  = lin >> 3;
        bch[i]   = lin & 7;
        bsoff[i] = brow[i] * BK + ((bch[i] ^ (brow[i] & 7)) << 3);
    }

    auto load_stage = [&](int stage, int kt) {
        __nv_bfloat16* tA = sA + (size_t)stage * BM * BK;
        __nv_bfloat16* tB = sB + (size_t)stage * BN * BK;
        const __nv_bfloat16* gA = gA0 + kt * BK;
        const __nv_bfloat16* gB = gB0 + kt * BK;
        #pragma unroll
        for (int i = 0; i < 4; i++)
            cp_async16(smem_u32(tA + asoff[i]),
                       gA + (size_t)arow[i] * Kdim + ach[i] * 8);
        #pragma unroll
        for (int i = 0; i < 8; i++)
            cp_async16(smem_u32(tB + bsoff[i]),
                       gB + (size_t)brow[i] * Kdim + bch[i] * 8);
    };

    #pragma unroll
    for (int s = 0; s < STAGES - 1; s++) { load_stage(s, s); cp_commit(); }

    float acc[4][8][4];
    #pragma unroll
    for (int im = 0; im < 4; im++)
        #pragma unroll
        for (int in = 0; in < 8; in++)
            #pragma unroll
            for (int j = 0; j < 4; j++) acc[im][in][j] = 0.f;

    for (int kt = 0; kt < KTILES; kt++) {
        cp_wait<STAGES - 2>();
        __syncthreads();

        const int nf = kt + STAGES - 1;
        if (nf < KTILES) load_stage(nf % STAGES, nf);
        cp_commit();

        const __nv_bfloat16* tA = sA + (size_t)(kt % STAGES) * BM * BK;
        const __nv_bfloat16* tB = sB + (size_t)(kt % STAGES) * BN * BK;

        #pragma unroll
        for (int kk = 0; kk < BK / 16; kk++) {   // 4 k16 steps
            // A fragments: 4 m16 tiles (warp rows 64)
            uint32_t af[4][4];
            #pragma unroll
            for (int im = 0; im < 4; im++) {
                int row = wm * 64 + im * 16 + (lane & 15);
                int ch  = kk * 2 + (lane >> 4);
                uint32_t addr = smem_u32(tA + row * BK + ((ch ^ (row & 7)) << 3));
                ldmatrix_x4(af[im][0], af[im][1], af[im][2], af[im][3], addr);
            }
            // B fragments: 4 n16 groups -> 8 n8 frags (warp cols 64)
            uint32_t bfr[8][2];
            #pragma unroll
            for (int ib = 0; ib < 4; ib++) {
                int row = wn * 64 + ib * 16 + (lane & 15);
                int ch  = kk * 2 + (lane >> 4);
                uint32_t addr = smem_u32(tB + row * BK + ((ch ^ (row & 7)) << 3));
                uint32_t r0, r1, r2, r3;
                ldmatrix_x4(r0, r1, r2, r3, addr);
                bfr[ib * 2 + 0][0] = r0; bfr[ib * 2 + 0][1] = r2;
                bfr[ib * 2 + 1][0] = r1; bfr[ib * 2 + 1][1] = r3;
            }
            #pragma unroll
            for (int im = 0; im < 4; im++)
                #pragma unroll
                for (int in = 0; in < 8; in++)
                    mma_16816(acc[im][in], af[im], bfr[in]);
        }
    }

    // Epilogue: bf16-round (reference output is bf16 upcast to fp32), store fp32
    const int m0 = bm * BM + wm * 64;
    const int n0 = bn * BN + wn * 64;
    #pragma unroll
    for (int im = 0; im < 4; im++) {
        #pragma unroll
        for (int in = 0; in < 8; in++) {
            int m = m0 + im * 16 + lg;
            int n = n0 + in * 8 + tig * 2;
            float2 v0 = make_float2(bf16r(acc[im][in][0]), bf16r(acc[im][in][1]));
            float2 v1 = make_float2(bf16r(acc[im][in][2]), bf16r(acc[im][in][3]));
            *reinterpret_cast<float2*>(C + (size_t)m * Ndim + n) = v0;
            *reinterpret_cast<float2*>(C + (size_t)(m + 8) * Ndim + n) = v1;
        }
    }
}

// ---------------------------------------------------------------------------
extern "C" void kernel_launch(void* const* d_in, const int* in_sizes, int n_in,
                              void* d_out, int out_size) {
    const float* x = (const float*)d_in[0];   // [16384,4096] fp32 (bf16-valued)
    const int*   w = (const int*)d_in[1];     // [16384,4096] int32
    const float* s = (const float*)d_in[2];   // [16384]      fp32 (bf16-valued)
    float*     out = (float*)d_out;           // [16384,16384] fp32

    {   // dequant
        size_t quads = (size_t)Ndim * Kdim / 4;
        dequant_kernel<<<(unsigned)(quads / 256), 256>>>(w, s);
    }
    {   // x convert
        size_t quads = (size_t)Mdim * Kdim / 4;
        xconv_kernel<<<(unsigned)(quads / 256), 256>>>(x);
    }
    {   // GEMM
        size_t smem_bytes = (size_t)STAGES * (BM + BN) * BK * sizeof(__nv_bfloat16); // 144 KB
        cudaFuncSetAttribute(gemm_kernel, cudaFuncAttributeMaxDynamicSharedMemorySize,
                             (int)smem_bytes);
        unsigned grid = (Mdim / BM) * (Ndim / BN);   // 8192 CTAs
        gemm_kernel<<<grid, THREADS, smem_bytes>>>(out);
    }
}

// round 15
// speedup vs baseline: 1.0807x; 1.0807x over previous
#include <cuda_runtime.h>
#include <cuda_bf16.h>
#include <cstdint>

// Problem dims (fixed)
static constexpr int Mdim = 16384;   // B*S
static constexpr int Ndim = 16384;   // DOUT
static constexpr int Kdim = 4096;    // DIN

// GEMM tiling: CTA 128x128, 4 warps (2x2), warp tile 64x64, BK=64, 3 stages
static constexpr int BM = 128, BN = 128, BK = 64;
static constexpr int STAGES = 3;
static constexpr int THREADS = 128;
static constexpr int KTILES = Kdim / BK;     // 64

// Scratch (device globals; no allocation). 128 MiB each.
__device__ __nv_bfloat16 g_wdeq[(size_t)Ndim * Kdim];
__device__ __nv_bfloat16 g_xbf [(size_t)Mdim * Kdim];

// ---------------------------------------------------------------------------
// Merged pre-pass: blocks [0, WQ/256) dequant w; rest convert x.
//   wdeq = bf16_round(float(w) * s)  (exact operands, single rounding ==
//          reference bf16*bf16);  xbf = bf16(x) (exact: x is bf16-valued fp32)
// ---------------------------------------------------------------------------
static constexpr unsigned WBLOCKS = (unsigned)((size_t)Ndim * Kdim / 4 / 256);  // 65536
static constexpr unsigned XBLOCKS = (unsigned)((size_t)Mdim * Kdim / 4 / 256);  // 65536

__global__ __launch_bounds__(256) void prepass_kernel(
    const int* __restrict__ w, const float* __restrict__ s,
    const float* __restrict__ x)
{
    unsigned b = blockIdx.x;
    if (b < WBLOCKS) {
        size_t q = (size_t)b * 256 + threadIdx.x;          // one int4 = 4 weights
        int row = (int)(q >> 10);                          // Kdim/4 quads per row
        float sc = s[row];
        int4 qv = reinterpret_cast<const int4*>(w)[q];
        __nv_bfloat162 r01 = __floats2bfloat162_rn((float)qv.x * sc, (float)qv.y * sc);
        __nv_bfloat162 r23 = __floats2bfloat162_rn((float)qv.z * sc, (float)qv.w * sc);
        __nv_bfloat162 pack[2] = {r01, r23};
        *reinterpret_cast<uint2*>(&g_wdeq[q * 4]) = *reinterpret_cast<uint2*>(pack);
    } else {
        size_t q = (size_t)(b - WBLOCKS) * 256 + threadIdx.x;   // one float4
        float4 v = reinterpret_cast<const float4*>(x)[q];
        __nv_bfloat162 r01 = __floats2bfloat162_rn(v.x, v.y);
        __nv_bfloat162 r23 = __floats2bfloat162_rn(v.z, v.w);
        __nv_bfloat162 pack[2] = {r01, r23};
        *reinterpret_cast<uint2*>(&g_xbf[q * 4]) = *reinterpret_cast<uint2*>(pack);
    }
}

// ---------------------------------------------------------------------------
// Helpers
// ---------------------------------------------------------------------------
__device__ __forceinline__ uint32_t smem_u32(const void* p) {
    return (uint32_t)__cvta_generic_to_shared(p);
}
__device__ __forceinline__ void cp_async16(uint32_t saddr, const void* g) {
    asm volatile("cp.async.cg.shared.global [%0], [%1], 16;\n" :: "r"(saddr), "l"(g));
}
__device__ __forceinline__ void cp_commit() { asm volatile("cp.async.commit_group;\n"); }
template<int N> __device__ __forceinline__ void cp_wait() {
    asm volatile("cp.async.wait_group %0;\n" :: "n"(N));
}
__device__ __forceinline__ void ldmatrix_x4(uint32_t &r0, uint32_t &r1,
                                            uint32_t &r2, uint32_t &r3, uint32_t addr) {
    asm volatile("ldmatrix.sync.aligned.m8n8.x4.shared.b16 {%0,%1,%2,%3}, [%4];\n"
                 : "=r"(r0), "=r"(r1), "=r"(r2), "=r"(r3) : "r"(addr));
}
__device__ __forceinline__ void mma_16816(float* c, const uint32_t* a, const uint32_t* b) {
    asm volatile(
        "mma.sync.aligned.m16n8k16.row.col.f32.bf16.bf16.f32 "
        "{%0,%1,%2,%3}, {%4,%5,%6,%7}, {%8,%9}, {%0,%1,%2,%3};\n"
        : "+f"(c[0]), "+f"(c[1]), "+f"(c[2]), "+f"(c[3])
        : "r"(a[0]), "r"(a[1]), "r"(a[2]), "r"(a[3]), "r"(b[0]), "r"(b[1]));
}
__device__ __forceinline__ float bf16r(float v) {
    return __bfloat162float(__float2bfloat16_rn(v));
}

// ---------------------------------------------------------------------------
// bf16 GEMM: C[M,N] = X[M,K] @ Wd[N,K]^T, fp32 accum, bf16-rounded fp32 out.
// R13 shape, but 2 CTAs/SM (independent-CTA latency hiding, separate barriers).
// ---------------------------------------------------------------------------
__global__ __launch_bounds__(THREADS, 2) void gemm_kernel(float* __restrict__ C)
{
    extern __shared__ __nv_bfloat16 smem[];
    __nv_bfloat16* sA = smem;                               // STAGES * BM * BK
    __nv_bfloat16* sB = smem + (size_t)STAGES * BM * BK;    // STAGES * BN * BK

    // CTA swizzle: groups of 16 M-tiles, N fast within a group (L2 reuse)
    const int tiles_n = Ndim / BN;     // 128
    const int GROUP = 16;
    const int per_group = GROUP * tiles_n;
    const int g_ = blockIdx.x / per_group;
    const int r_ = blockIdx.x % per_group;
    const int bm = g_ * GROUP + (r_ % GROUP);
    const int bn = r_ / GROUP;

    const int tid  = threadIdx.x;
    const int warp = tid >> 5;
    const int lane = tid & 31;
    const int wm = warp >> 1;          // 0..1 -> 64 rows
    const int wn = warp & 1;           // 0..1 -> 64 cols
    const int lg  = lane >> 2;         // 0..7
    const int tig = lane & 3;          // 0..3

    const __nv_bfloat16* gA0 = g_xbf  + (size_t)(bm * BM) * Kdim;
    const __nv_bfloat16* gB0 = g_wdeq + (size_t)(bn * BN) * Kdim;

    // cp.async slots: 128 rows x 8 chunks(16B) per tile = 1024; 8 per thread
    int lrow[8], lch[8], lsoff[8];
    #pragma unroll
    for (int i = 0; i < 8; i++) {
        int lin = tid + i * THREADS;
        lrow[i]  = lin >> 3;
        lch[i]   = lin & 7;
        lsoff[i] = lrow[i] * BK + ((lch[i] ^ (lrow[i] & 7)) << 3);
    }

    auto load_stage = [&](int stage, int kt) {
        __nv_bfloat16* tA = sA + (size_t)stage * BM * BK;
        __nv_bfloat16* tB = sB + (size_t)stage * BN * BK;
        const __nv_bfloat16* gA = gA0 + kt * BK;
        const __nv_bfloat16* gB = gB0 + kt * BK;
        #pragma unroll
        for (int i = 0; i < 8; i++) {
            const size_t goff = (size_t)lrow[i] * Kdim + lch[i] * 8;
            cp_async16(smem_u32(tA + lsoff[i]), gA + goff);
            cp_async16(smem_u32(tB + lsoff[i]), gB + goff);
        }
    };

    #pragma unroll
    for (int s = 0; s < STAGES - 1; s++) { load_stage(s, s); cp_commit(); }

    float acc[4][8][4];
    #pragma unroll
    for (int im = 0; im < 4; im++)
        #pragma unroll
        for (int in = 0; in < 8; in++)
            #pragma unroll
            for (int j = 0; j < 4; j++) acc[im][in][j] = 0.f;

    for (int kt = 0; kt < KTILES; kt++) {
        cp_wait<STAGES - 2>();
        __syncthreads();

        const int nf = kt + STAGES - 1;
        if (nf < KTILES) load_stage(nf % STAGES, nf);
        cp_commit();

        const __nv_bfloat16* tA = sA + (size_t)(kt % STAGES) * BM * BK;
        const __nv_bfloat16* tB = sB + (size_t)(kt % STAGES) * BN * BK;

        #pragma unroll
        for (int kk = 0; kk < BK / 16; kk++) {   // 4 k16 steps
            // A fragments: 4 m16 tiles (warp rows 64)
            uint32_t af[4][4];
            #pragma unroll
            for (int im = 0; im < 4; im++) {
                int row = wm * 64 + im * 16 + (lane & 15);
                int ch  = kk * 2 + (lane >> 4);
                uint32_t addr = smem_u32(tA + row * BK + ((ch ^ (row & 7)) << 3));
                ldmatrix_x4(af[im][0], af[im][1], af[im][2], af[im][3], addr);
            }
            // B fragments: 4 n16 groups -> 8 n8 frags (warp cols 64)
            uint32_t bfr[8][2];
            #pragma unroll
            for (int ib = 0; ib < 4; ib++) {
                int row = wn * 64 + ib * 16 + (lane & 15);
                int ch  = kk * 2 + (lane >> 4);
                uint32_t addr = smem_u32(tB + row * BK + ((ch ^ (row & 7)) << 3));
                uint32_t r0, r1, r2, r3;
                ldmatrix_x4(r0, r1, r2, r3, addr);
                bfr[ib * 2 + 0][0] = r0; bfr[ib * 2 + 0][1] = r2;
                bfr[ib * 2 + 1][0] = r1; bfr[ib * 2 + 1][1] = r3;
            }
            #pragma unroll
            for (int im = 0; im < 4; im++)
                #pragma unroll
                for (int in = 0; in < 8; in++)
                    mma_16816(acc[im][in], af[im], bfr[in]);
        }
    }

    // Epilogue: bf16-round (reference output is bf16 upcast to fp32), store fp32
    const int m0 = bm * BM + wm * 64;
    const int n0 = bn * BN + wn * 64;
    #pragma unroll
    for (int im = 0; im < 4; im++) {
        #pragma unroll
        for (int in = 0; in < 8; in++) {
            int m = m0 + im * 16 + lg;
            int n = n0 + in * 8 + tig * 2;
            float2 v0 = make_float2(bf16r(acc[im][in][0]), bf16r(acc[im][in][1]));
            float2 v1 = make_float2(bf16r(acc[im][in][2]), bf16r(acc[im][in][3]));
            *reinterpret_cast<float2*>(C + (size_t)m * Ndim + n) = v0;
            *reinterpret_cast<float2*>(C + (size_t)(m + 8) * Ndim + n) = v1;
        }
    }
}

// ---------------------------------------------------------------------------
extern "C" void kernel_launch(void* const* d_in, const int* in_sizes, int n_in,
                              void* d_out, int out_size) {
    const float* x = (const float*)d_in[0];   // [16384,4096] fp32 (bf16-valued)
    const int*   w = (const int*)d_in[1];     // [16384,4096] int32
    const float* s = (const float*)d_in[2];   // [16384]      fp32 (bf16-valued)
    float*     out = (float*)d_out;           // [16384,16384] fp32

    // merged pre-pass (one launch)
    prepass_kernel<<<WBLOCKS + XBLOCKS, 256>>>(w, s, x);

    // GEMM
    size_t smem_bytes = (size_t)STAGES * (BM + BN) * BK * sizeof(__nv_bfloat16); // 96 KB
    cudaFuncSetAttribute(gemm_kernel, cudaFuncAttributeMaxDynamicSharedMemorySize,
                         (int)smem_bytes);
    unsigned grid = (Mdim / BM) * (Ndim / BN);   // 16384 CTAs
    gemm_kernel<<<grid, THREADS, smem_bytes>>>(out);
}

// round 16
// speedup vs baseline: 1.0834x; 1.0024x over previous
#include <cuda_runtime.h>
#include <cuda_bf16.h>
#include <cstdint>

// Problem dims (fixed)
static constexpr int Mdim = 16384;   // B*S
static constexpr int Ndim = 16384;   // DOUT
static constexpr int Kdim = 4096;    // DIN

// GEMM tiling: CTA 128x128, 4 warps (2x2), warp tile 64x64, BK=64, 3 stages
static constexpr int BM = 128, BN = 128, BK = 64;
static constexpr int STAGES = 3;
static constexpr int THREADS = 128;
static constexpr int KTILES = Kdim / BK;     // 64

// Scratch (device globals; no allocation). 128 MiB each.
__device__ __nv_bfloat16 g_wdeq[(size_t)Ndim * Kdim];
__device__ __nv_bfloat16 g_xbf [(size_t)Mdim * Kdim];

// ---------------------------------------------------------------------------
// Merged pre-pass: blocks [0, WBLOCKS) dequant w; rest convert x.
// ---------------------------------------------------------------------------
static constexpr unsigned WBLOCKS = (unsigned)((size_t)Ndim * Kdim / 4 / 256);  // 65536
static constexpr unsigned XBLOCKS = (unsigned)((size_t)Mdim * Kdim / 4 / 256);  // 65536

__global__ __launch_bounds__(256) void prepass_kernel(
    const int* __restrict__ w, const float* __restrict__ s,
    const float* __restrict__ x)
{
    unsigned b = blockIdx.x;
    if (b < WBLOCKS) {
        size_t q = (size_t)b * 256 + threadIdx.x;          // one int4 = 4 weights
        int row = (int)(q >> 10);                          // Kdim/4 quads per row
        float sc = s[row];
        int4 qv = reinterpret_cast<const int4*>(w)[q];
        __nv_bfloat162 r01 = __floats2bfloat162_rn((float)qv.x * sc, (float)qv.y * sc);
        __nv_bfloat162 r23 = __floats2bfloat162_rn((float)qv.z * sc, (float)qv.w * sc);
        __nv_bfloat162 pack[2] = {r01, r23};
        *reinterpret_cast<uint2*>(&g_wdeq[q * 4]) = *reinterpret_cast<uint2*>(pack);
    } else {
        size_t q = (size_t)(b - WBLOCKS) * 256 + threadIdx.x;   // one float4
        float4 v = reinterpret_cast<const float4*>(x)[q];
        __nv_bfloat162 r01 = __floats2bfloat162_rn(v.x, v.y);
        __nv_bfloat162 r23 = __floats2bfloat162_rn(v.z, v.w);
        __nv_bfloat162 pack[2] = {r01, r23};
        *reinterpret_cast<uint2*>(&g_xbf[q * 4]) = *reinterpret_cast<uint2*>(pack);
    }
}

// ---------------------------------------------------------------------------
// Helpers
// ---------------------------------------------------------------------------
__device__ __forceinline__ uint32_t smem_u32(const void* p) {
    return (uint32_t)__cvta_generic_to_shared(p);
}
__device__ __forceinline__ void cp_async16(uint32_t saddr, const void* g) {
    asm volatile("cp.async.cg.shared.global [%0], [%1], 16;\n" :: "r"(saddr), "l"(g));
}
__device__ __forceinline__ void cp_commit() { asm volatile("cp.async.commit_group;\n"); }
template<int N> __device__ __forceinline__ void cp_wait() {
    asm volatile("cp.async.wait_group %0;\n" :: "n"(N));
}
__device__ __forceinline__ void ldmatrix_x4(uint32_t &r0, uint32_t &r1,
                                            uint32_t &r2, uint32_t &r3, uint32_t addr) {
    asm volatile("ldmatrix.sync.aligned.m8n8.x4.shared.b16 {%0,%1,%2,%3}, [%4];\n"
                 : "=r"(r0), "=r"(r1), "=r"(r2), "=r"(r3) : "r"(addr));
}
__device__ __forceinline__ void mma_16816(float* c, const uint32_t* a, const uint32_t* b) {
    asm volatile(
        "mma.sync.aligned.m16n8k16.row.col.f32.bf16.bf16.f32 "
        "{%0,%1,%2,%3}, {%4,%5,%6,%7}, {%8,%9}, {%0,%1,%2,%3};\n"
        : "+f"(c[0]), "+f"(c[1]), "+f"(c[2]), "+f"(c[3])
        : "r"(a[0]), "r"(a[1]), "r"(a[2]), "r"(a[3]), "r"(b[0]), "r"(b[1]));
}
__device__ __forceinline__ float bf16r(float v) {
    return __bfloat162float(__float2bfloat16_rn(v));
}

// ---------------------------------------------------------------------------
// bf16 GEMM: C[M,N] = X[M,K] @ Wd[N,K]^T, fp32 accum, bf16-rounded fp32 out.
// Software-pipelined fragments: prefetch kk+1's LDSM before kk's 32 HMMAs.
// ---------------------------------------------------------------------------
__global__ __launch_bounds__(THREADS, 2) void gemm_kernel(float* __restrict__ C)
{
    extern __shared__ __nv_bfloat16 smem[];
    __nv_bfloat16* sA = smem;                               // STAGES * BM * BK
    __nv_bfloat16* sB = smem + (size_t)STAGES * BM * BK;    // STAGES * BN * BK

    // CTA swizzle: groups of 16 M-tiles, N fast within a group (L2 reuse)
    const int tiles_n = Ndim / BN;     // 128
    const int GROUP = 16;
    const int per_group = GROUP * tiles_n;
    const int g_ = blockIdx.x / per_group;
    const int r_ = blockIdx.x % per_group;
    const int bm = g_ * GROUP + (r_ % GROUP);
    const int bn = r_ / GROUP;

    const int tid  = threadIdx.x;
    const int warp = tid >> 5;
    const int lane = tid & 31;
    const int wm = warp >> 1;          // 0..1 -> 64 rows
    const int wn = warp & 1;           // 0..1 -> 64 cols
    const int lg  = lane >> 2;         // 0..7
    const int tig = lane & 3;          // 0..3

    const __nv_bfloat16* gA0 = g_xbf  + (size_t)(bm * BM) * Kdim;
    const __nv_bfloat16* gB0 = g_wdeq + (size_t)(bn * BN) * Kdim;

    // cp.async slots: 128 rows x 8 chunks(16B) per tile = 1024; 8 per thread
    int lrow[8], lch[8], lsoff[8];
    #pragma unroll
    for (int i = 0; i < 8; i++) {
        int lin = tid + i * THREADS;
        lrow[i]  = lin >> 3;
        lch[i]   = lin & 7;
        lsoff[i] = lrow[i] * BK + ((lch[i] ^ (lrow[i] & 7)) << 3);
    }

    auto load_stage = [&](int stage, int kt) {
        __nv_bfloat16* tA = sA + (size_t)stage * BM * BK;
        __nv_bfloat16* tB = sB + (size_t)stage * BN * BK;
        const __nv_bfloat16* gA = gA0 + kt * BK;
        const __nv_bfloat16* gB = gB0 + kt * BK;
        #pragma unroll
        for (int i = 0; i < 8; i++) {
            const size_t goff = (size_t)lrow[i] * Kdim + lch[i] * 8;
            cp_async16(smem_u32(tA + lsoff[i]), gA + goff);
            cp_async16(smem_u32(tB + lsoff[i]), gB + goff);
        }
    };

    // LDSM row/base indices (kk-invariant parts)
    const int a_row[4] = { wm * 64 + 0 * 16 + (lane & 15), wm * 64 + 1 * 16 + (lane & 15),
                           wm * 64 + 2 * 16 + (lane & 15), wm * 64 + 3 * 16 + (lane & 15) };
    const int b_row[4] = { wn * 64 + 0 * 16 + (lane & 15), wn * 64 + 1 * 16 + (lane & 15),
                           wn * 64 + 2 * 16 + (lane & 15), wn * 64 + 3 * 16 + (lane & 15) };
    const int ch_hi = (lane >> 4);     // 0..1

    // Fragment double buffers
    uint32_t af[2][4][4];
    uint32_t bfr[2][4][4];             // [ib][{r0,r1,r2,r3}] raw ldmatrix regs

    auto load_frags = [&](const __nv_bfloat16* tA, const __nv_bfloat16* tB,
                          int kk, int buf) {
        const int ch = kk * 2 + ch_hi;
        #pragma unroll
        for (int im = 0; im < 4; im++) {
            int row = a_row[im];
            uint32_t addr = smem_u32(tA + row * BK + ((ch ^ (row & 7)) << 3));
            ldmatrix_x4(af[buf][im][0], af[buf][im][1], af[buf][im][2], af[buf][im][3], addr);
        }
        #pragma unroll
        for (int ib = 0; ib < 4; ib++) {
            int row = b_row[ib];
            uint32_t addr = smem_u32(tB + row * BK + ((ch ^ (row & 7)) << 3));
            ldmatrix_x4(bfr[buf][ib][0], bfr[buf][ib][1], bfr[buf][ib][2], bfr[buf][ib][3], addr);
        }
    };

    auto do_mma = [&](int buf, float (*acc)[8][4]) {
        #pragma unroll
        for (int im = 0; im < 4; im++)
            #pragma unroll
            for (int ib = 0; ib < 4; ib++) {
                uint32_t b0[2] = { bfr[buf][ib][0], bfr[buf][ib][2] };
                uint32_t b1[2] = { bfr[buf][ib][1], bfr[buf][ib][3] };
                mma_16816(acc[im][ib * 2 + 0], af[buf][im], b0);
                mma_16816(acc[im][ib * 2 + 1], af[buf][im], b1);
            }
    };

    #pragma unroll
    for (int s = 0; s < STAGES - 1; s++) { load_stage(s, s); cp_commit(); }

    float acc[4][8][4];
    #pragma unroll
    for (int im = 0; im < 4; im++)
        #pragma unroll
        for (int in = 0; in < 8; in++)
            #pragma unroll
            for (int j = 0; j < 4; j++) acc[im][in][j] = 0.f;

    for (int kt = 0; kt < KTILES; kt++) {
        cp_wait<STAGES - 2>();
        __syncthreads();

        const __nv_bfloat16* tA = sA + (size_t)(kt % STAGES) * BM * BK;
        const __nv_bfloat16* tB = sB + (size_t)(kt % STAGES) * BN * BK;

        // Prime fragment pipeline for this tile
        load_frags(tA, tB, 0, 0);

        // Issue next global stage while frags are in flight
        const int nf = kt + STAGES - 1;
        if (nf < KTILES) load_stage(nf % STAGES, nf);
        cp_commit();

        #pragma unroll
        for (int kk = 0; kk < BK / 16; kk++) {   // 4 k16 steps
            if (kk < BK / 16 - 1) load_frags(tA, tB, kk + 1, (kk + 1) & 1);
            do_mma(kk & 1, acc);
        }
    }

    // Epilogue: bf16-round (reference output is bf16 upcast to fp32), store fp32
    const int m0 = bm * BM + wm * 64;
    const int n0 = bn * BN + wn * 64;
    #pragma unroll
    for (int im = 0; im < 4; im++) {
        #pragma unroll
        for (int in = 0; in < 8; in++) {
            int m = m0 + im * 16 + lg;
            int n = n0 + in * 8 + tig * 2;
            float2 v0 = make_float2(bf16r(acc[im][in][0]), bf16r(acc[im][in][1]));
            float2 v1 = make_float2(bf16r(acc[im][in][2]), bf16r(acc[im][in][3]));
            *reinterpret_cast<float2*>(C + (size_t)m * Ndim + n) = v0;
            *reinterpret_cast<float2*>(C + (size_t)(m + 8) * Ndim + n) = v1;
        }
    }
}

// ---------------------------------------------------------------------------
extern "C" void kernel_launch(void* const* d_in, const int* in_sizes, int n_in,
                              void* d_out, int out_size) {
    const float* x = (const float*)d_in[0];   // [16384,4096] fp32 (bf16-valued)
    const int*   w = (const int*)d_in[1];     // [16384,4096] int32
    const float* s = (const float*)d_in[2];   // [16384]      fp32 (bf16-valued)
    float*     out = (float*)d_out;           // [16384,16384] fp32

    // merged pre-pass (one launch)
    prepass_kernel<<<WBLOCKS + XBLOCKS, 256>>>(w, s, x);

    // GEMM
    size_t smem_bytes = (size_t)STAGES * (BM + BN) * BK * sizeof(__nv_bfloat16); // 96 KB
    cudaFuncSetAttribute(gemm_kernel, cudaFuncAttributeMaxDynamicSharedMemorySize,
                         (int)smem_bytes);
    unsigned grid = (Mdim / BM) * (Ndim / BN);   // 16384 CTAs
    gemm_kernel<<<grid, THREADS, smem_bytes>>>(out);
}